// round 2
// baseline (speedup 1.0000x reference)
#include <cuda_runtime.h>
#include <math.h>

#define N_  256
#define T_  128
#define I_  512
#define H_  512
#define G_  2048            // 4*H
#define M_  (N_*T_)         // 32768
#define NTH (N_*T_*H_)      // 16777216

// ---------------- scratch (device globals: no allocation allowed) -----------
__device__ float g_gx[(size_t)T_ * N_ * G_];   // [t][n][4H]  (256 MB)
__device__ float g_gates[N_ * G_];             // per-step gates (2 MB)
__device__ float g_h[N_ * H_];
__device__ float g_c[N_ * H_];
__device__ float g_hs[(size_t)M_ * H_];        // [n][t][H]   (64 MB)

// ---------------- shared 128x128 fp32 GEMM tile (C = A * B^T), lda=ldb=512 --
__device__ __forceinline__ void gemm128(const float* __restrict__ A,
                                        const float* __restrict__ B,
                                        int K0, int K1, float acc[8][8])
{
    __shared__ float As[8][132];
    __shared__ float Bs[8][132];
    const int tid  = threadIdx.x;
    const int lrow = tid >> 1;          // 0..127
    const int lcol = (tid & 1) << 2;    // 0 or 4
    const int ty   = tid >> 4;          // 0..15
    const int tx   = tid & 15;          // 0..15
    const float* Ap = A + lrow * 512 + lcol;
    const float* Bp = B + lrow * 512 + lcol;

    for (int k = K0; k < K1; k += 8) {
        float4 av = *(const float4*)(Ap + k);
        float4 bv = *(const float4*)(Bp + k);
        __syncthreads();
        As[lcol+0][lrow]=av.x; As[lcol+1][lrow]=av.y;
        As[lcol+2][lrow]=av.z; As[lcol+3][lrow]=av.w;
        Bs[lcol+0][lrow]=bv.x; Bs[lcol+1][lrow]=bv.y;
        Bs[lcol+2][lrow]=bv.z; Bs[lcol+3][lrow]=bv.w;
        __syncthreads();
        #pragma unroll
        for (int kk = 0; kk < 8; kk++) {
            float4 a0 = *(const float4*)&As[kk][ty*8];
            float4 a1 = *(const float4*)&As[kk][ty*8+4];
            float4 b0 = *(const float4*)&Bs[kk][tx*8];
            float4 b1 = *(const float4*)&Bs[kk][tx*8+4];
            float ar[8] = {a0.x,a0.y,a0.z,a0.w,a1.x,a1.y,a1.z,a1.w};
            float br[8] = {b0.x,b0.y,b0.z,b0.w,b1.x,b1.y,b1.z,b1.w};
            #pragma unroll
            for (int i=0;i<8;i++)
                #pragma unroll
                for (int j=0;j<8;j++)
                    acc[i][j] = fmaf(ar[i], br[j], acc[i][j]);
        }
    }
}

// ---------------- kernels ---------------------------------------------------
__global__ void init_kernel(const float* __restrict__ hx, const float* __restrict__ cx)
{
    int idx = blockIdx.x * 256 + threadIdx.x;     // N*H
    int n = idx >> 9, k = idx & 511;
    g_h[idx] = hx[(size_t)n * T_ * H_ + k];       // hx[:,0,:]
    g_c[idx] = cx[(size_t)n * T_ * H_ + k];
}

// gx[t][n][g] = x[n,t,:] @ W_ih^T + b_ih + b_hh   (block bm == sample n)
__global__ void gemm_gx_kernel(const float* __restrict__ x,
                               const float* __restrict__ W_ih,
                               const float* __restrict__ b_ih,
                               const float* __restrict__ b_hh)
{
    float acc[8][8];
    #pragma unroll
    for (int i=0;i<8;i++)
        #pragma unroll
        for (int j=0;j<8;j++) acc[i][j]=0.f;

    const int bn = blockIdx.x, bm = blockIdx.y;
    gemm128(x + (size_t)bm*128*512, W_ih + (size_t)bn*128*512, 0, 512, acc);

    const int ty = threadIdx.x >> 4, tx = threadIdx.x & 15;
    const int col0 = bn*128 + tx*8;
    #pragma unroll
    for (int i=0;i<8;i++) {
        int t = ty*8 + i;                          // T_==128: local row == t
        float* dst = g_gx + ((size_t)t * N_ + bm) * G_ + col0;
        #pragma unroll
        for (int j=0;j<8;j++)
            dst[j] = acc[i][j] + b_ih[col0+j] + b_hh[col0+j];
    }
}

__global__ void copy_gx_kernel(int t)
{
    int v = blockIdx.x * 256 + threadIdx.x;        // N*G/4
    ((float4*)g_gates)[v] = ((const float4*)(g_gx + (size_t)t * N_ * G_))[v];
}

// gates[n,:] += r(n,t) * (h[n,:] @ W_hh^T), K-split over blockIdx.z
__global__ void gemm_step_kernel(const float* __restrict__ W_hh,
                                 const int* __restrict__ is_init, int t)
{
    float acc[8][8];
    #pragma unroll
    for (int i=0;i<8;i++)
        #pragma unroll
        for (int j=0;j<8;j++) acc[i][j]=0.f;

    const int bn = blockIdx.x, bm = blockIdx.y, kz = blockIdx.z;
    gemm128(g_h + (size_t)bm*128*512, W_hh + (size_t)bn*128*512,
            kz*128, kz*128 + 128, acc);

    const int ty = threadIdx.x >> 4, tx = threadIdx.x & 15;
    const int col0 = bn*128 + tx*8;
    #pragma unroll
    for (int i=0;i<8;i++) {
        int n = bm*128 + ty*8 + i;
        if (is_init[n*T_ + t] == 0) {              // r == 1
            float* dst = g_gates + (size_t)n * G_ + col0;
            #pragma unroll
            for (int j=0;j<8;j++) atomicAdd(dst + j, acc[i][j]);
        }                                          // r == 0: contribution is 0
    }
}

__device__ __forceinline__ float sigm(float x){ return 1.f / (1.f + expf(-x)); }

__global__ void pointwise_kernel(const int* __restrict__ is_init, int t)
{
    int idx = blockIdx.x * 256 + threadIdx.x;      // N*H
    int n = idx >> 9, k = idx & 511;
    float r = is_init[n*T_ + t] ? 0.f : 1.f;
    const float* g = g_gates + (size_t)n * G_;
    float ig = sigm(g[k]);
    float fg = sigm(g[H_ + k]);
    float gg = tanhf(g[2*H_ + k]);
    float og = sigm(g[3*H_ + k]);
    float cn = fg * (g_c[idx] * r) + ig * gg;
    float hn = og * tanhf(cn);
    g_c[idx] = cn;
    g_h[idx] = hn;
    g_hs[((size_t)n * T_ + t) * H_ + k] = hn;
}

// out[:NTH] = mish(hs @ W_out^T + b_out)
__global__ void gemm_out_kernel(const float* __restrict__ W_out,
                                const float* __restrict__ b_out,
                                float* __restrict__ out)
{
    float acc[8][8];
    #pragma unroll
    for (int i=0;i<8;i++)
        #pragma unroll
        for (int j=0;j<8;j++) acc[i][j]=0.f;

    const int bn = blockIdx.x, bm = blockIdx.y;
    gemm128(g_hs + (size_t)bm*128*512, W_out + (size_t)bn*128*512, 0, 512, acc);

    const int ty = threadIdx.x >> 4, tx = threadIdx.x & 15;
    const int col0 = bn*128 + tx*8;
    const int row0 = bm*128 + ty*8;
    #pragma unroll
    for (int i=0;i<8;i++) {
        #pragma unroll
        for (int j=0;j<8;j++) {
            float z  = acc[i][j] + b_out[col0+j];
            float sp = (z > 15.f) ? z : log1pf(expf(z));
            out[(size_t)(row0+i) * H_ + col0 + j] = z * tanhf(sp);
        }
    }
}

__global__ void replicate_kernel(float* __restrict__ out)
{
    int v = blockIdx.x * 256 + threadIdx.x;        // NTH/4
    int k4 = v & 127;
    int n  = v >> 14;                              // T*H/4 = 16384
    float4 hv = ((const float4*)g_h)[n*128 + k4];
    float4 cv = ((const float4*)g_c)[n*128 + k4];
    ((float4*)(out + NTH))[v]     = hv;
    ((float4*)(out + 2*(size_t)NTH))[v] = cv;
}

// ---------------- launcher ---------------------------------------------------
extern "C" void kernel_launch(void* const* d_in, const int* in_sizes, int n_in,
                              void* d_out, int out_size)
{
    const float* x     = (const float*)d_in[0];
    const int*   isi   = (const int*)  d_in[1];
    const float* hx    = (const float*)d_in[2];
    const float* cx    = (const float*)d_in[3];
    const float* W_ih  = (const float*)d_in[4];
    const float* W_hh  = (const float*)d_in[5];
    const float* b_ih  = (const float*)d_in[6];
    const float* b_hh  = (const float*)d_in[7];
    const float* W_out = (const float*)d_in[8];
    const float* b_out = (const float*)d_in[9];
    float* out = (float*)d_out;

    init_kernel<<<512, 256>>>(hx, cx);
    gemm_gx_kernel<<<dim3(16, 256), 256>>>(x, W_ih, b_ih, b_hh);

    for (int t = 0; t < T_; t++) {
        copy_gx_kernel<<<512, 256>>>(t);
        gemm_step_kernel<<<dim3(16, 2, 4), 256>>>(W_hh, isi, t);
        pointwise_kernel<<<512, 256>>>(isi, t);
    }

    gemm_out_kernel<<<dim3(4, 256), 256>>>(W_out, b_out, out);
    replicate_kernel<<<16384, 256>>>(out);
}